// round 3
// baseline (speedup 1.0000x reference)
#include <cuda_runtime.h>

// StructuralLoss: predictions (64, 8192, 60) fp32 -> scalar.
// 20-float unit: bid_l=v[2l], ask_l=v[10+2l];
// viol = sum max(ask_l-ask_{l+1},0) + sum max(bid_{l+1}-bid_l,0) + max(bid0-ask0,0)
// out = (1/64) * sum over all units.
//
// Coalesced scheme: 5 float4 per unit; lane l (<30) of a warp loads float4
// (group*30 + l) -> consecutive lanes load consecutive 16B -> one contiguous
// 480B segment per warp load. Cross-float4 terms via 2 warp shuffles.

#define NBLOCKS 1184
#define NTHREADS 256
#define WARPS_PER_BLOCK (NTHREADS / 32)

__device__ float g_partials[NBLOCKS];
__device__ unsigned int g_ticket;   // zero-init; last block resets each run

// Per-lane contribution for one group's float4. j = lane%5, valid = lane<30.
__device__ __forceinline__ float group_terms(float4 w, int j, bool valid)
{
    // n1: next lane's w.x  (= v[4(j+1)] of same unit for j<4)
    // n2: lane+2's w.z     (= v10 = ask0, needed by j==0 for spread)
    float n1 = __shfl_down_sync(0xffffffffu, w.x, 1);
    float n2 = __shfl_down_sync(0xffffffffu, w.z, 2);

    float sign = (j <= 1) ? 1.0f : -1.0f;
    float d1 = sign * (w.z - w.x);   // intra-float4 pair
    float d2 = sign * (n1 - w.z);    // cross-float4 pair

    float t = 0.0f;
    if (j != 2) t += fmaxf(d1, 0.0f);          // j==2 has no intra term
    if (j != 4) t += fmaxf(d2, 0.0f);          // j==4 has no cross term
    if (j == 0) t += fmaxf(w.x - n2, 0.0f);    // spread: bid0 - ask0
    return valid ? t : 0.0f;
}

__global__ __launch_bounds__(NTHREADS) void viol_kernel(
    const float4* __restrict__ pred4, int n_groups, float* __restrict__ out)
{
    const int lane   = threadIdx.x & 31;
    const int gwarp  = (blockIdx.x * WARPS_PER_BLOCK) + (threadIdx.x >> 5);
    const int twarps = NBLOCKS * WARPS_PER_BLOCK;
    const int j      = lane % 5;
    const bool valid = lane < 30;

    float acc = 0.0f;

    // 2 groups (12 units, 960B) per warp-iteration.
    const int n_pairs = n_groups >> 1;
    for (int p = gwarp; p < n_pairs; p += twarps) {
        int g0 = 2 * p;
        float4 w0 = make_float4(0.f, 0.f, 0.f, 0.f);
        float4 w1 = make_float4(0.f, 0.f, 0.f, 0.f);
        if (valid) {
            w0 = pred4[(long long)g0 * 30 + lane];
            w1 = pred4[(long long)(g0 + 1) * 30 + lane];
        }
        acc += group_terms(w0, j, valid);
        acc += group_terms(w1, j, valid);
    }
    // Odd-group tail (not hit for this problem: n_groups = 262144 even).
    if (n_groups & 1) {
        int g = n_groups - 1;
        if (gwarp == 0) {
            float4 w = make_float4(0.f, 0.f, 0.f, 0.f);
            if (valid) w = pred4[(long long)g * 30 + lane];
            acc += group_terms(w, j, valid);
        }
    }

    // Deterministic block reduction
    __shared__ float s[WARPS_PER_BLOCK];
    #pragma unroll
    for (int o = 16; o > 0; o >>= 1)
        acc += __shfl_down_sync(0xffffffffu, acc, o);
    if (lane == 0) s[threadIdx.x >> 5] = acc;
    __syncthreads();

    __shared__ bool s_is_last;
    if (threadIdx.x < 32) {
        float v = (threadIdx.x < WARPS_PER_BLOCK) ? s[threadIdx.x] : 0.0f;
        #pragma unroll
        for (int o = 16; o > 0; o >>= 1)
            v += __shfl_down_sync(0xffffffffu, v, o);
        if (threadIdx.x == 0) {
            g_partials[blockIdx.x] = v;
            __threadfence();
            unsigned int t = atomicAdd(&g_ticket, 1u);
            s_is_last = (t == NBLOCKS - 1);
        }
    }
    __syncthreads();

    // Last block: final reduce (deterministic order).
    if (s_is_last) {
        float facc = 0.0f;
        for (int i = threadIdx.x; i < NBLOCKS; i += NTHREADS)
            facc += g_partials[i];
        #pragma unroll
        for (int o = 16; o > 0; o >>= 1)
            facc += __shfl_down_sync(0xffffffffu, facc, o);
        __shared__ float fs[WARPS_PER_BLOCK];
        if ((threadIdx.x & 31) == 0) fs[threadIdx.x >> 5] = facc;
        __syncthreads();
        if (threadIdx.x == 0) {
            float t = 0.0f;
            #pragma unroll
            for (int i = 0; i < WARPS_PER_BLOCK; i++) t += fs[i];
            out[0] = t * (1.0f / 64.0f);
            g_ticket = 0;   // reset for next graph replay
        }
    }
}

extern "C" void kernel_launch(void* const* d_in, const int* in_sizes, int n_in,
                              void* d_out, int out_size)
{
    const float4* pred4 = (const float4*)d_in[0];
    float* out = (float*)d_out;
    int n_units  = in_sizes[0] / 20;   // 1,572,864
    int n_groups = n_units / 6;        // 262,144 (6 units = 30 float4 per warp-group)

    viol_kernel<<<NBLOCKS, NTHREADS>>>(pred4, n_groups, out);
}

// round 4
// speedup vs baseline: 1.0082x; 1.0082x over previous
#include <cuda_runtime.h>

// StructuralLoss: predictions (64, 8192, 60) fp32 -> scalar.
// 20-float unit: bid_l=v[2l], ask_l=v[10+2l];
// viol = sum max(ask_l-ask_{l+1},0) + sum max(bid_{l+1}-bid_l,0) + max(bid0-ask0,0)
// out = (1/64) * sum over all units.
//
// Coalesced: 6 units = 30 float4 per warp "group"; lane l (<30) loads float4
// (group*30 + l). Cross-float4 terms via 2 warp shuffles. 4 groups unrolled
// per iteration for MLP=4.

#define NBLOCKS 1184
#define NTHREADS 256
#define WARPS_PER_BLOCK (NTHREADS / 32)

__device__ float g_partials[NBLOCKS];
__device__ unsigned int g_ticket;   // zero-init; last block resets each run

__global__ __launch_bounds__(NTHREADS) void viol_kernel(
    const float4* __restrict__ pred4, int n_groups, float* __restrict__ out)
{
    const int lane   = threadIdx.x & 31;
    const int gwarp  = (blockIdx.x * WARPS_PER_BLOCK) + (threadIdx.x >> 5);
    const int twarps = NBLOCKS * WARPS_PER_BLOCK;
    const int j      = lane % 5;
    const bool valid = lane < 30;

    // Per-lane constant masks (hoisted out of the loop).
    const float sign = (j <= 1) ? 1.0f : -1.0f;
    const float c1 = (valid && j != 2) ? 1.0f : 0.0f;  // intra-float4 pair
    const float c2 = (valid && j != 4) ? 1.0f : 0.0f;  // cross-float4 pair
    const float cs = (valid && j == 0) ? 1.0f : 0.0f;  // spread bid0-ask0

    float acc = 0.0f;

    #define GROUP_TERMS(w)                                                 \
        do {                                                               \
            float n1 = __shfl_down_sync(0xffffffffu, (w).x, 1);            \
            float n2 = __shfl_down_sync(0xffffffffu, (w).z, 2);            \
            float d1 = sign * ((w).z - (w).x);                             \
            float d2 = sign * (n1 - (w).z);                                \
            float ds = (w).x - n2;                                         \
            acc = fmaf(c1, fmaxf(d1, 0.0f), acc);                          \
            acc = fmaf(c2, fmaxf(d2, 0.0f), acc);                          \
            acc = fmaf(cs, fmaxf(ds, 0.0f), acc);                          \
        } while (0)

    // 4 groups (24 units, 1920B) per warp-iteration -> 4 LDGs in flight.
    const int n_quads = n_groups >> 2;
    for (int q = gwarp; q < n_quads; q += twarps) {
        long long b = (long long)(4 * q) * 30 + lane;
        float4 w0 = make_float4(0.f, 0.f, 0.f, 0.f);
        float4 w1 = w0, w2 = w0, w3 = w0;
        if (valid) {
            w0 = __ldcs(&pred4[b]);
            w1 = __ldcs(&pred4[b + 30]);
            w2 = __ldcs(&pred4[b + 60]);
            w3 = __ldcs(&pred4[b + 90]);
        }
        GROUP_TERMS(w0);
        GROUP_TERMS(w1);
        GROUP_TERMS(w2);
        GROUP_TERMS(w3);
    }
    // Remainder groups (none for this shape: 262144 % 4 == 0).
    {
        int rem = n_groups & 3;
        int g = (n_quads << 2) + gwarp;
        if (gwarp < rem) {
            float4 w = make_float4(0.f, 0.f, 0.f, 0.f);
            if (valid) w = __ldcs(&pred4[(long long)g * 30 + lane]);
            GROUP_TERMS(w);
        }
    }
    #undef GROUP_TERMS

    // Deterministic block reduction.
    __shared__ float s[WARPS_PER_BLOCK];
    #pragma unroll
    for (int o = 16; o > 0; o >>= 1)
        acc += __shfl_down_sync(0xffffffffu, acc, o);
    if (lane == 0) s[threadIdx.x >> 5] = acc;
    __syncthreads();

    __shared__ bool s_is_last;
    if (threadIdx.x < 32) {
        float v = (threadIdx.x < WARPS_PER_BLOCK) ? s[threadIdx.x] : 0.0f;
        #pragma unroll
        for (int o = 16; o > 0; o >>= 1)
            v += __shfl_down_sync(0xffffffffu, v, o);
        if (threadIdx.x == 0) {
            g_partials[blockIdx.x] = v;
            __threadfence();
            unsigned int t = atomicAdd(&g_ticket, 1u);
            s_is_last = (t == NBLOCKS - 1);
        }
    }
    __syncthreads();

    // Last block finishes the reduction (deterministic order).
    if (s_is_last) {
        float facc = 0.0f;
        for (int i = threadIdx.x; i < NBLOCKS; i += NTHREADS)
            facc += g_partials[i];
        #pragma unroll
        for (int o = 16; o > 0; o >>= 1)
            facc += __shfl_down_sync(0xffffffffu, facc, o);
        __shared__ float fs[WARPS_PER_BLOCK];
        if ((threadIdx.x & 31) == 0) fs[threadIdx.x >> 5] = facc;
        __syncthreads();
        if (threadIdx.x == 0) {
            float t = 0.0f;
            #pragma unroll
            for (int i = 0; i < WARPS_PER_BLOCK; i++) t += fs[i];
            out[0] = t * (1.0f / 64.0f);
            g_ticket = 0;   // reset for next graph replay
        }
    }
}

extern "C" void kernel_launch(void* const* d_in, const int* in_sizes, int n_in,
                              void* d_out, int out_size)
{
    const float4* pred4 = (const float4*)d_in[0];
    float* out = (float*)d_out;
    int n_units  = in_sizes[0] / 20;   // 1,572,864
    int n_groups = n_units / 6;        // 262,144

    viol_kernel<<<NBLOCKS, NTHREADS>>>(pred4, n_groups, out);
}

// round 5
// speedup vs baseline: 1.0904x; 1.0815x over previous
#include <cuda_runtime.h>

// StructuralLoss: predictions (64, 8192, 60) fp32 -> scalar.
// 20-float unit: bid_l=v[2l], ask_l=v[10+2l];
// viol = sum max(ask_l-ask_{l+1},0) + sum max(bid_{l+1}-bid_l,0) + max(bid0-ask0,0)
// out = (1/64) * sum over all units.
//
// Coalesced: 6 units = 30 float4 per warp "group"; lane l (<30) loads float4
// (group*30 + l). Cross-float4 terms via 2 warp shuffles. 4 groups unrolled
// per iteration (MLP=4) + __launch_bounds__(256,8) to hold 8 CTAs/SM.

#define NBLOCKS 1184
#define NTHREADS 256
#define WARPS_PER_BLOCK (NTHREADS / 32)

__device__ float g_partials[NBLOCKS];
__device__ unsigned int g_ticket;   // zero-init; last block resets each run

__global__ __launch_bounds__(NTHREADS, 8) void viol_kernel(
    const float4* __restrict__ pred4, int n_groups, float* __restrict__ out)
{
    const int lane   = threadIdx.x & 31;
    const int gwarp  = (blockIdx.x * WARPS_PER_BLOCK) + (threadIdx.x >> 5);
    const int twarps = NBLOCKS * WARPS_PER_BLOCK;
    const int j      = lane % 5;
    const bool valid = lane < 30;

    // Per-lane constant masks (hoisted out of the loop).
    const float sign = (j <= 1) ? 1.0f : -1.0f;
    const float c1 = (valid && j != 2) ? 1.0f : 0.0f;  // intra-float4 pair
    const float c2 = (valid && j != 4) ? 1.0f : 0.0f;  // cross-float4 pair
    const float cs = (valid && j == 0) ? 1.0f : 0.0f;  // spread bid0-ask0

    float acc = 0.0f;

    #define GROUP_TERMS(w)                                                 \
        do {                                                               \
            float n1 = __shfl_down_sync(0xffffffffu, (w).x, 1);            \
            float n2 = __shfl_down_sync(0xffffffffu, (w).z, 2);            \
            float d1 = sign * ((w).z - (w).x);                             \
            float d2 = sign * (n1 - (w).z);                                \
            float ds = (w).x - n2;                                         \
            acc = fmaf(c1, fmaxf(d1, 0.0f), acc);                          \
            acc = fmaf(c2, fmaxf(d2, 0.0f), acc);                          \
            acc = fmaf(cs, fmaxf(ds, 0.0f), acc);                          \
        } while (0)

    // 4 groups (24 units, 1920B) per warp-iteration -> 4 LDGs in flight.
    const int n_quads = n_groups >> 2;
    for (int q = gwarp; q < n_quads; q += twarps) {
        const float4* b = pred4 + ((long long)(4 * q) * 30 + lane);
        float4 w0 = make_float4(0.f, 0.f, 0.f, 0.f);
        float4 w1 = w0, w2 = w0, w3 = w0;
        if (valid) {
            w0 = __ldcs(b);
            w1 = __ldcs(b + 30);
            w2 = __ldcs(b + 60);
            w3 = __ldcs(b + 90);
        }
        GROUP_TERMS(w0);
        GROUP_TERMS(w1);
        GROUP_TERMS(w2);
        GROUP_TERMS(w3);
    }
    // Remainder groups (none for this shape: 262144 % 4 == 0).
    {
        int rem = n_groups & 3;
        int g = (n_quads << 2) + gwarp;
        if (gwarp < rem) {
            float4 w = make_float4(0.f, 0.f, 0.f, 0.f);
            if (valid) w = __ldcs(&pred4[(long long)g * 30 + lane]);
            GROUP_TERMS(w);
        }
    }
    #undef GROUP_TERMS

    // Deterministic block reduction.
    __shared__ float s[WARPS_PER_BLOCK];
    #pragma unroll
    for (int o = 16; o > 0; o >>= 1)
        acc += __shfl_down_sync(0xffffffffu, acc, o);
    if (lane == 0) s[threadIdx.x >> 5] = acc;
    __syncthreads();

    __shared__ bool s_is_last;
    if (threadIdx.x < 32) {
        float v = (threadIdx.x < WARPS_PER_BLOCK) ? s[threadIdx.x] : 0.0f;
        #pragma unroll
        for (int o = 16; o > 0; o >>= 1)
            v += __shfl_down_sync(0xffffffffu, v, o);
        if (threadIdx.x == 0) {
            g_partials[blockIdx.x] = v;
            __threadfence();
            unsigned int t = atomicAdd(&g_ticket, 1u);
            s_is_last = (t == NBLOCKS - 1);
        }
    }
    __syncthreads();

    // Last block finishes the reduction (deterministic order).
    if (s_is_last) {
        float facc = 0.0f;
        for (int i = threadIdx.x; i < NBLOCKS; i += NTHREADS)
            facc += g_partials[i];
        #pragma unroll
        for (int o = 16; o > 0; o >>= 1)
            facc += __shfl_down_sync(0xffffffffu, facc, o);
        __shared__ float fs[WARPS_PER_BLOCK];
        if ((threadIdx.x & 31) == 0) fs[threadIdx.x >> 5] = facc;
        __syncthreads();
        if (threadIdx.x == 0) {
            float t = 0.0f;
            #pragma unroll
            for (int i = 0; i < WARPS_PER_BLOCK; i++) t += fs[i];
            out[0] = t * (1.0f / 64.0f);
            g_ticket = 0;   // reset for next graph replay
        }
    }
}

extern "C" void kernel_launch(void* const* d_in, const int* in_sizes, int n_in,
                              void* d_out, int out_size)
{
    const float4* pred4 = (const float4*)d_in[0];
    float* out = (float*)d_out;
    int n_units  = in_sizes[0] / 20;   // 1,572,864
    int n_groups = n_units / 6;        // 262,144

    viol_kernel<<<NBLOCKS, NTHREADS>>>(pred4, n_groups, out);
}